// round 13
// baseline (speedup 1.0000x reference)
#include <cuda_runtime.h>
#include <cuda_bf16.h>
#include <cstdint>

#define NN 50000
#define NE 800000
#define NT 12500            // NE / 64 edge-tiles
#define INV_SQRT_DEG 0.25f  // 1/sqrt(16)

// ---------------- scratch ----------
__device__ float g_s [NN * 16];    // s = node_scalars @ W_in_s
__device__ float g_v [NN * 48];    // v[n][w][c]
__device__ float g_as[NN * 32];    // scalar accumulator
__device__ float g_av[NN * 144];   // vector accumulator [n][(p*3+c)][u(16)]
__device__ float g_w [(size_t)NE * 80];  // per-edge MLP outputs [e][p(5)][u(16)]

// ---------------- f32x2 packed-math helpers (sm_103a FFMA2) ----------------
typedef unsigned long long ull;

__device__ __forceinline__ ull pack2(float x, float y) {
    ull r; asm("mov.b64 %0, {%1, %2};" : "=l"(r) : "f"(x), "f"(y)); return r;
}
__device__ __forceinline__ void unpack2(ull v, float& x, float& y) {
    asm("mov.b64 {%0, %1}, %2;" : "=f"(x), "=f"(y) : "l"(v));
}
__device__ __forceinline__ ull ffma2(ull a, ull b, ull c) {
    ull d; asm("fma.rn.f32x2 %0, %1, %2, %3;" : "=l"(d) : "l"(a), "l"(b), "l"(c));
    return d;
}
__device__ __forceinline__ void lds_v2u64(unsigned int addr, ull& a, ull& b) {
    asm volatile("ld.shared.v2.u64 {%0, %1}, [%2];"
                 : "=l"(a), "=l"(b) : "r"(addr));
}
// pack two f32 into bf16x2 (lo = first arg, hi = second arg)
__device__ __forceinline__ unsigned int bf16x2(float lo, float hi) {
    unsigned int r;
    asm("cvt.rn.bf16x2.f32 %0, %1, %2;" : "=r"(r) : "f"(hi), "f"(lo));
    return r;
}
__device__ __forceinline__ void mma_bf16(
    float& c0, float& c1, float& c2, float& c3,
    unsigned int a0, unsigned int a1, unsigned int a2, unsigned int a3,
    unsigned int b0, unsigned int b1)
{
    asm volatile(
        "mma.sync.aligned.m16n8k16.row.col.f32.bf16.bf16.f32 "
        "{%0,%1,%2,%3}, {%4,%5,%6,%7}, {%8,%9}, {%0,%1,%2,%3};"
        : "+f"(c0), "+f"(c1), "+f"(c2), "+f"(c3)
        : "r"(a0), "r"(a1), "r"(a2), "r"(a3), "r"(b0), "r"(b1));
}

// ======================= kernel Z: zero accumulators ======================
__global__ void __launch_bounds__(256) zero_kernel()
{
    int i = blockIdx.x * blockDim.x + threadIdx.x;
    float4 z = make_float4(0.f, 0.f, 0.f, 0.f);
    if (i < NN * 36) ((float4*)g_av)[i] = z;
    if (i < NN * 8)  ((float4*)g_as)[i] = z;
}

// ======================= kernel A: node pre (4 threads / node) ============
__global__ void __launch_bounds__(256) pre_kernel(
    const float* __restrict__ node_scalars,
    const float* __restrict__ node_vectors,
    const float* __restrict__ W_in_s,
    const float* __restrict__ W_in_v)
{
    __shared__ __align__(16) float sWs[16 * 16];
    __shared__ __align__(16) float sWv[16 * 16];
    for (int i = threadIdx.x; i < 256; i += blockDim.x) {
        sWs[i] = W_in_s[i];
        sWv[i] = W_in_v[i];
    }
    __syncthreads();

    int t = blockIdx.x * blockDim.x + threadIdx.x;
    int n  = t >> 2;
    int qh = t & 3;          // w-quarter: w in [4qh, 4qh+4)
    if (n >= NN) return;

    unsigned int wsb = (unsigned int)__cvta_generic_to_shared(sWs) + qh * 16;
    unsigned int wvb = (unsigned int)__cvta_generic_to_shared(sWv) + qh * 16;

    float nsv[16];
    {
        const float4* p = (const float4*)(node_scalars + (size_t)n * 16);
#pragma unroll
        for (int k = 0; k < 4; k++) {
            float4 q = p[k];
            nsv[4*k+0]=q.x; nsv[4*k+1]=q.y; nsv[4*k+2]=q.z; nsv[4*k+3]=q.w;
        }
    }
    float vin[48];
    {
        const float4* p = (const float4*)(node_vectors + (size_t)n * 48);
#pragma unroll
        for (int k = 0; k < 12; k++) {
            float4 q = p[k];
            vin[4*k+0]=q.x; vin[4*k+1]=q.y; vin[4*k+2]=q.z; vin[4*k+3]=q.w;
        }
    }

    ull sacc2[2] = {0ull, 0ull};
    ull vacc2[3][2];
#pragma unroll
    for (int c = 0; c < 3; c++) { vacc2[c][0] = 0ull; vacc2[c][1] = 0ull; }

#pragma unroll 4
    for (int u = 0; u < 16; u++) {
        ull w0, w1;
        lds_v2u64(wsb + u * 64, w0, w1);   // W_in_s[u][4qh..4qh+4)
        ull aa = pack2(nsv[u], nsv[u]);
        sacc2[0] = ffma2(aa, w0, sacc2[0]);
        sacc2[1] = ffma2(aa, w1, sacc2[1]);

        ull v0, v1;
        lds_v2u64(wvb + u * 64, v0, v1);
#pragma unroll
        for (int c = 0; c < 3; c++) {
            ull mm = pack2(vin[u*3+c], vin[u*3+c]);
            vacc2[c][0] = ffma2(mm, v0, vacc2[c][0]);
            vacc2[c][1] = ffma2(mm, v1, vacc2[c][1]);
        }
    }

    {
        float s4[4];
        unpack2(sacc2[0], s4[0], s4[1]);
        unpack2(sacc2[1], s4[2], s4[3]);
        *(float4*)(g_s + (size_t)n * 16 + 4*qh) = make_float4(s4[0], s4[1], s4[2], s4[3]);
    }
    {
        float vv[3][4];
#pragma unroll
        for (int c = 0; c < 3; c++) {
            unpack2(vacc2[c][0], vv[c][0], vv[c][1]);
            unpack2(vacc2[c][1], vv[c][2], vv[c][3]);
        }
        float o12[12];
#pragma unroll
        for (int w = 0; w < 4; w++) {
            o12[3*w+0] = vv[0][w];
            o12[3*w+1] = vv[1][w];
            o12[3*w+2] = vv[2][w];
        }
        float4* p = (float4*)(g_v + (size_t)n * 48 + 12*qh);
        p[0] = make_float4(o12[0], o12[1], o12[2], o12[3]);
        p[1] = make_float4(o12[4], o12[5], o12[6], o12[7]);
        p[2] = make_float4(o12[8], o12[9], o12[10], o12[11]);
    }
}

// ======================= kernel B1: radial MLP (bf16 tensor-core) =========
// Block = 64 edges. Phase 1: h = silu(emb@W1+b1) in fp32, stored bf16x2 in smem
// (double-buffered). Phase 2: w = h @ W2 via mma.m16n8k16 bf16.
// ONE __syncthreads per tile: p1(t+2) is reachable only after the sync in
// iteration t+1, which guarantees all threads finished p2(t) on that buffer.
#define SH_STRIDE 36  // uints; A-load bank = 4g+tg -> conflict-free
#define SB_STRIDE 88  // uints; B-load bank = 24tg+g -> conflict-free
__global__ void __launch_bounds__(256) mlp_kernel(
    const float* __restrict__ radial_emb,
    const float* __restrict__ mlp_w1,
    const float* __restrict__ mlp_b1,
    const float* __restrict__ mlp_w2)
{
    __shared__ __align__(16) float sW1[8 * 64];
    __shared__ __align__(16) float sb1[64];
    __shared__ __align__(16) unsigned int sB[32 * SB_STRIDE];      // W2 bf16x2
    __shared__ __align__(16) unsigned int sH[2][64 * SH_STRIDE];   // h bf16x2, double-buffered

    for (int i = threadIdx.x; i < 8 * 64; i += blockDim.x) sW1[i] = mlp_w1[i];
    for (int i = threadIdx.x; i < 64; i += blockDim.x)     sb1[i] = mlp_b1[i];
    for (int i = threadIdx.x; i < 32 * 80; i += blockDim.x) {
        int jp = i / 80, n = i % 80;
        sB[jp * SB_STRIDE + n] = bf16x2(mlp_w2[(2*jp) * 80 + n],
                                        mlp_w2[(2*jp + 1) * 80 + n]);
    }
    __syncthreads();

    int lane = threadIdx.x & 31;
    int warp = threadIdx.x >> 5;
    int g  = lane >> 2;          // group id 0..7
    int tg = lane & 3;           // thread-in-group 0..3
    int eg   = warp >> 1;        // edge group 0..3 (16 edges each)
    int half = warp & 1;         // N-half: cols [40h, 40h+40)

    int edge_q = threadIdx.x >> 2;        // 0..63 (phase-1 edge)
    int jq     = (threadIdx.x & 3) * 16;  // phase-1 j range

    int par = 0;
    for (int tile = blockIdx.x; tile < NT; tile += gridDim.x) {
        int e0 = tile * 64;
        unsigned int* sHp = sH[par];

        // ---- phase 1: layer 1 + silu (fp32 exact), write bf16x2 h ----
        {
            const float4* pe = (const float4*)(radial_emb + (size_t)(e0 + edge_q) * 8);
            float4 ea = pe[0], eb = pe[1];
            float em[8] = {ea.x, ea.y, ea.z, ea.w, eb.x, eb.y, eb.z, eb.w};
#pragma unroll
            for (int k = 0; k < 4; k++) {
                float4 acc = *(const float4*)(sb1 + jq + 4*k);
#pragma unroll
                for (int i = 0; i < 8; i++) {
                    float4 wv = *(const float4*)(sW1 + i * 64 + jq + 4*k);
                    acc.x += em[i] * wv.x;
                    acc.y += em[i] * wv.y;
                    acc.z += em[i] * wv.z;
                    acc.w += em[i] * wv.w;
                }
                float s0 = __fdividef(acc.x, 1.f + __expf(-acc.x));
                float s1 = __fdividef(acc.y, 1.f + __expf(-acc.y));
                float s2 = __fdividef(acc.z, 1.f + __expf(-acc.z));
                float s3 = __fdividef(acc.w, 1.f + __expf(-acc.w));
                uint2 uu;
                uu.x = bf16x2(s0, s1);
                uu.y = bf16x2(s2, s3);
                *(uint2*)(sHp + edge_q * SH_STRIDE + jq / 2 + 2*k) = uu;
            }
        }
        __syncthreads();

        // ---- phase 2: layer 2 GEMM via bf16 MMA (K=16 per inst, 4 iters) ----
        float c[5][4];
#pragma unroll
        for (int nn = 0; nn < 5; nn++)
#pragma unroll
            for (int q = 0; q < 4; q++) c[nn][q] = 0.f;

        const unsigned int* h0 = sHp + (eg * 16 + g) * SH_STRIDE;
        const unsigned int* h1 = h0 + 8 * SH_STRIDE;
#pragma unroll
        for (int kk = 0; kk < 4; kk++) {
            unsigned int a0 = h0[kk*8 + tg];
            unsigned int a1 = h1[kk*8 + tg];
            unsigned int a2 = h0[kk*8 + tg + 4];
            unsigned int a3 = h1[kk*8 + tg + 4];
            const unsigned int* b0p = sB + (kk*8 + tg)     * SB_STRIDE + half * 40 + g;
            const unsigned int* b1p = sB + (kk*8 + tg + 4) * SB_STRIDE + half * 40 + g;
#pragma unroll
            for (int nn = 0; nn < 5; nn++) {
                mma_bf16(c[nn][0], c[nn][1], c[nn][2], c[nn][3],
                         a0, a1, a2, a3, b0p[nn*8], b1p[nn*8]);
            }
        }

        // ---- store: c0,c1 -> (row g, cols 2t,2t+1); c2,c3 -> row g+8 ----
        {
            int er = e0 + eg * 16 + g;
            float* w0 = g_w + (size_t)er * 80 + half * 40 + 2 * tg;
            float* w1 = g_w + (size_t)(er + 8) * 80 + half * 40 + 2 * tg;
#pragma unroll
            for (int nn = 0; nn < 5; nn++) {
                *(float2*)(w0 + nn * 8) = make_float2(c[nn][0], c[nn][1]);
                *(float2*)(w1 + nn * 8) = make_float2(c[nn][2], c[nn][3]);
            }
        }
        par ^= 1;   // no trailing sync — next tile writes the other buffer
    }
}

// ======================= kernel B2: messages + scatter (4 threads / edge) =
__global__ void __launch_bounds__(256) scatter_kernel(
    const float* __restrict__ edge_sh,
    const int*   __restrict__ senders,
    const int*   __restrict__ receivers)
{
    int t = blockIdx.x * blockDim.x + threadIdx.x;
    int e = t >> 2;
    int q = t & 3;           // u-chunk: u in [4q, 4q+4)
    if (e >= NE) return;

    const float* wp = g_w + (size_t)e * 80 + 4 * q;
    float4 w0 = *(const float4*)(wp);
    float4 w1 = *(const float4*)(wp + 16);
    float4 w2 = *(const float4*)(wp + 32);
    float4 w3 = *(const float4*)(wp + 48);
    float4 w4 = *(const float4*)(wp + 64);
    float p0[4] = {w0.x, w0.y, w0.z, w0.w};
    float p1[4] = {w1.x, w1.y, w1.z, w1.w};
    float p2[4] = {w2.x, w2.y, w2.z, w2.w};
    float p3[4] = {w3.x, w3.y, w3.z, w3.w};
    float p4[4] = {w4.x, w4.y, w4.z, w4.w};

    int snd = senders[e];
    int rcv = receivers[e];
    float4 sh4 = *(const float4*)(edge_sh + (size_t)e * 4);
    float Y0 = sh4.x, Yx = sh4.y, Yy = sh4.z, Yz = sh4.w;

    float4 xs4 = ((const float4*)(g_s + (size_t)snd * 16))[q];
    float xs[4] = {xs4.x, xs4.y, xs4.z, xs4.w};
    float xv[12];
    {
        const float4* pv = (const float4*)(g_v + (size_t)snd * 48);
        float4 q0 = pv[3*q+0], q1 = pv[3*q+1], q2 = pv[3*q+2];
        xv[0]=q0.x; xv[1]=q0.y; xv[2]=q0.z; xv[3]=q0.w;
        xv[4]=q1.x; xv[5]=q1.y; xv[6]=q1.z; xv[7]=q1.w;
        xv[8]=q2.x; xv[9]=q2.y; xv[10]=q2.z; xv[11]=q2.w;
    }

    float ms1[4], ms2[4], v1m[3][4], v2m[3][4], v3m[3][4];
#pragma unroll
    for (int i = 0; i < 4; i++) {
        float ax = xv[3*i+0], ay = xv[3*i+1], az = xv[3*i+2];
        float xsu = xs[i];
        ms1[i] = p0[i] * xsu * Y0;
        ms2[i] = p1[i] * (ax*Yx + ay*Yy + az*Yz);
        float al = p2[i] * xsu;
        v1m[0][i] = al * Yx; v1m[1][i] = al * Yy; v1m[2][i] = al * Yz;
        float be = p3[i] * Y0;
        v2m[0][i] = be * ax; v2m[1][i] = be * ay; v2m[2][i] = be * az;
        float ga = p4[i];
        v3m[0][i] = ga * (ay*Yz - az*Yy);
        v3m[1][i] = ga * (az*Yx - ax*Yz);
        v3m[2][i] = ga * (ax*Yy - ay*Yx);
    }

    float* as_base = g_as + (size_t)rcv * 32;
    float* av_base = g_av + (size_t)rcv * 144;
    atomicAdd((float4*)(as_base + 4*q),
              make_float4(ms1[0], ms1[1], ms1[2], ms1[3]));
    atomicAdd((float4*)(as_base + 16 + 4*q),
              make_float4(ms2[0], ms2[1], ms2[2], ms2[3]));
#pragma unroll
    for (int c = 0; c < 3; c++) {
        atomicAdd((float4*)(av_base + (0*3 + c) * 16 + 4*q),
                  make_float4(v1m[c][0], v1m[c][1], v1m[c][2], v1m[c][3]));
        atomicAdd((float4*)(av_base + (1*3 + c) * 16 + 4*q),
                  make_float4(v2m[c][0], v2m[c][1], v2m[c][2], v2m[c][3]));
        atomicAdd((float4*)(av_base + (2*3 + c) * 16 + 4*q),
                  make_float4(v3m[c][0], v3m[c][1], v3m[c][2], v3m[c][3]));
    }
}

// ======================= kernel C: node post (4 threads / node) ===========
__global__ void __launch_bounds__(256) post_kernel(
    const float* __restrict__ node_scalars,
    const float* __restrict__ node_vectors,
    const int*   __restrict__ species,
    const float* __restrict__ W_out_s,   // [32][32]
    const float* __restrict__ W_out_v,   // [48][16]
    const float* __restrict__ sc_s,      // [4][16][32]
    const float* __restrict__ sc_v,      // [4][16][16]
    float* __restrict__ out)             // [NN][64]
{
    __shared__ __align__(16) float sWs [32 * 32];
    __shared__ __align__(16) float sWv [48 * 16];
    __shared__ __align__(16) float sScs[4 * 16 * 32];
    __shared__ __align__(16) float sScv[4 * 16 * 16];
    for (int i = threadIdx.x; i < 32*32; i += blockDim.x) sWs[i] = W_out_s[i];
    for (int i = threadIdx.x; i < 48*16; i += blockDim.x) sWv[i] = W_out_v[i];
    for (int i = threadIdx.x; i < 4*16*32; i += blockDim.x) sScs[i] = sc_s[i];
    for (int i = threadIdx.x; i < 4*16*16; i += blockDim.x) sScv[i] = sc_v[i];
    __syncthreads();

    int t = blockIdx.x * blockDim.x + threadIdx.x;
    int n  = t >> 2;
    int qh = t & 3;          // w-quarter: w in [4qh, 4qh+4)
    if (n >= NN) return;

    int sp = species[n];

    unsigned int wsb  = (unsigned int)__cvta_generic_to_shared(sWs)  + qh * 16;
    unsigned int wvb  = (unsigned int)__cvta_generic_to_shared(sWv)  + qh * 16;
    unsigned int scsb = (unsigned int)__cvta_generic_to_shared(sScs) + sp * 2048 + qh * 16;
    unsigned int scvb = (unsigned int)__cvta_generic_to_shared(sScv) + sp * 1024 + qh * 16;

    // accumulators: 4 silu outs (cols 4qh..+4), 4 gate outs (cols 16+4qh..)
    ull psa[2] = {0ull, 0ull};
    ull psg[2] = {0ull, 0ull};

    {
        float asv[32];
        const float4* p = (const float4*)(g_as + (size_t)n * 32);
#pragma unroll
        for (int k = 0; k < 8; k++) {
            float4 q = p[k];
            asv[4*k+0]=q.x; asv[4*k+1]=q.y; asv[4*k+2]=q.z; asv[4*k+3]=q.w;
        }
#pragma unroll 4
        for (int k = 0; k < 32; k++) {
            float a = asv[k] * INV_SQRT_DEG;
            ull aa = pack2(a, a);
            ull r0, r1, r2, r3;
            lds_v2u64(wsb + k * 128,      r0, r1);   // silu cols
            lds_v2u64(wsb + k * 128 + 64, r2, r3);   // gate cols
            psa[0] = ffma2(aa, r0, psa[0]);
            psa[1] = ffma2(aa, r1, psa[1]);
            psg[0] = ffma2(aa, r2, psg[0]);
            psg[1] = ffma2(aa, r3, psg[1]);
        }
    }

    float nsv[16];
    {
        const float4* p = (const float4*)(node_scalars + (size_t)n * 16);
#pragma unroll
        for (int k = 0; k < 4; k++) {
            float4 q = p[k];
            nsv[4*k+0]=q.x; nsv[4*k+1]=q.y; nsv[4*k+2]=q.z; nsv[4*k+3]=q.w;
        }
    }
#pragma unroll 4
    for (int u = 0; u < 16; u++) {
        ull aa = pack2(nsv[u], nsv[u]);
        ull r0, r1, r2, r3;
        lds_v2u64(scsb + u * 128,      r0, r1);
        lds_v2u64(scsb + u * 128 + 64, r2, r3);
        psa[0] = ffma2(aa, r0, psa[0]);
        psa[1] = ffma2(aa, r1, psa[1]);
        psg[0] = ffma2(aa, r2, psg[0]);
        psg[1] = ffma2(aa, r3, psg[1]);
    }

    ull pv2[3][2];
#pragma unroll
    for (int c = 0; c < 3; c++) { pv2[c][0] = 0ull; pv2[c][1] = 0ull; }

    const float* av = g_av + (size_t)n * 144;
#pragma unroll
    for (int p = 0; p < 3; p++) {
        float m0[16], m1[16], m2[16];
        {
            const float4* q0 = (const float4*)(av + (p*3+0)*16);
            const float4* q1 = (const float4*)(av + (p*3+1)*16);
            const float4* q2 = (const float4*)(av + (p*3+2)*16);
#pragma unroll
            for (int k = 0; k < 4; k++) {
                float4 a = q0[k]; m0[4*k]=a.x; m0[4*k+1]=a.y; m0[4*k+2]=a.z; m0[4*k+3]=a.w;
                float4 b = q1[k]; m1[4*k]=b.x; m1[4*k+1]=b.y; m1[4*k+2]=b.z; m1[4*k+3]=b.w;
                float4 c4 = q2[k]; m2[4*k]=c4.x; m2[4*k+1]=c4.y; m2[4*k+2]=c4.z; m2[4*k+3]=c4.w;
            }
        }
#pragma unroll 4
        for (int u = 0; u < 16; u++) {
            ull r0, r1;
            lds_v2u64(wvb + (p*16 + u) * 64, r0, r1);
            ull mm0 = pack2(m0[u]*INV_SQRT_DEG, m0[u]*INV_SQRT_DEG);
            ull mm1 = pack2(m1[u]*INV_SQRT_DEG, m1[u]*INV_SQRT_DEG);
            ull mm2 = pack2(m2[u]*INV_SQRT_DEG, m2[u]*INV_SQRT_DEG);
            pv2[0][0] = ffma2(mm0, r0, pv2[0][0]);
            pv2[0][1] = ffma2(mm0, r1, pv2[0][1]);
            pv2[1][0] = ffma2(mm1, r0, pv2[1][0]);
            pv2[1][1] = ffma2(mm1, r1, pv2[1][1]);
            pv2[2][0] = ffma2(mm2, r0, pv2[2][0]);
            pv2[2][1] = ffma2(mm2, r1, pv2[2][1]);
        }
    }

    float vin[48];
    {
        const float4* p = (const float4*)(node_vectors + (size_t)n * 48);
#pragma unroll
        for (int k = 0; k < 12; k++) {
            float4 q = p[k];
            vin[4*k+0]=q.x; vin[4*k+1]=q.y; vin[4*k+2]=q.z; vin[4*k+3]=q.w;
        }
    }
#pragma unroll 4
    for (int u = 0; u < 16; u++) {
        ull r0, r1;
        lds_v2u64(scvb + u * 64, r0, r1);
        ull mm0 = pack2(vin[u*3+0], vin[u*3+0]);
        ull mm1 = pack2(vin[u*3+1], vin[u*3+1]);
        ull mm2 = pack2(vin[u*3+2], vin[u*3+2]);
        pv2[0][0] = ffma2(mm0, r0, pv2[0][0]);
        pv2[0][1] = ffma2(mm0, r1, pv2[0][1]);
        pv2[1][0] = ffma2(mm1, r0, pv2[1][0]);
        pv2[1][1] = ffma2(mm1, r1, pv2[1][1]);
        pv2[2][0] = ffma2(mm2, r0, pv2[2][0]);
        pv2[2][1] = ffma2(mm2, r1, pv2[2][1]);
    }

    float sa[4], sg[4], pvv[3][4];
    unpack2(psa[0], sa[0], sa[1]);
    unpack2(psa[1], sa[2], sa[3]);
    unpack2(psg[0], sg[0], sg[1]);
    unpack2(psg[1], sg[2], sg[3]);
#pragma unroll
    for (int c = 0; c < 3; c++) {
        unpack2(pv2[c][0], pvv[c][0], pvv[c][1]);
        unpack2(pv2[c][1], pvv[c][2], pvv[c][3]);
    }

    // out_s quarter: out[n][4qh..4qh+4)
    {
        float o4[4];
#pragma unroll
        for (int i = 0; i < 4; i++) {
            float x = sa[i];
            o4[i] = __fdividef(x, 1.f + __expf(-x)) + nsv[4*qh + i];
        }
        *(float4*)(out + (size_t)n * 64 + 4*qh) = make_float4(o4[0], o4[1], o4[2], o4[3]);
    }
    // out_v quarter: floats [16 + 12qh, +12)
    {
        float o12[12];
#pragma unroll
        for (int i = 0; i < 4; i++) {
            float g = __fdividef(1.f, 1.f + __expf(-sg[i]));
            int w = 4*qh + i;
            o12[3*i+0] = pvv[0][i] * g + vin[3*w+0];
            o12[3*i+1] = pvv[1][i] * g + vin[3*w+1];
            o12[3*i+2] = pvv[2][i] * g + vin[3*w+2];
        }
        float4* p = (float4*)(out + (size_t)n * 64 + 16 + 12*qh);
        p[0] = make_float4(o12[0], o12[1], o12[2], o12[3]);
        p[1] = make_float4(o12[4], o12[5], o12[6], o12[7]);
        p[2] = make_float4(o12[8], o12[9], o12[10], o12[11]);
    }
}

// ======================= launcher ========================================
extern "C" void kernel_launch(void* const* d_in, const int* in_sizes, int n_in,
                              void* d_out, int out_size)
{
    const float* node_scalars = (const float*)d_in[0];
    const float* node_vectors = (const float*)d_in[1];
    const float* edge_sh      = (const float*)d_in[2];
    const float* radial_emb   = (const float*)d_in[3];
    const int*   senders      = (const int*)  d_in[4];
    const int*   receivers    = (const int*)  d_in[5];
    const int*   species      = (const int*)  d_in[6];
    const float* W_in_s       = (const float*)d_in[7];
    const float* W_in_v       = (const float*)d_in[8];
    const float* mlp_w1       = (const float*)d_in[9];
    const float* mlp_b1       = (const float*)d_in[10];
    const float* mlp_w2       = (const float*)d_in[11];
    const float* W_out_s      = (const float*)d_in[12];
    const float* W_out_v      = (const float*)d_in[13];
    const float* sc_s         = (const float*)d_in[14];
    const float* sc_v         = (const float*)d_in[15];
    float* out = (float*)d_out;

    zero_kernel<<<(NN * 36 + 255) / 256, 256>>>();
    pre_kernel<<<(4 * NN + 255) / 256, 256>>>(node_scalars, node_vectors, W_in_s, W_in_v);
    mlp_kernel<<<1480, 256>>>(radial_emb, mlp_w1, mlp_b1, mlp_w2);
    scatter_kernel<<<(4 * NE + 255) / 256, 256>>>(edge_sh, senders, receivers);
    post_kernel<<<(4 * NN + 255) / 256, 256>>>(node_scalars, node_vectors, species,
                                               W_out_s, W_out_v, sc_s, sc_v, out);
}

// round 14
// speedup vs baseline: 1.0403x; 1.0403x over previous
#include <cuda_runtime.h>
#include <cuda_bf16.h>
#include <cstdint>

#define NN 50000
#define NE 800000
#define NT 12500            // NE / 64 edge-tiles
#define INV_SQRT_DEG 0.25f  // 1/sqrt(16)

// ---------------- scratch ----------
__device__ float g_s [NN * 16];    // s = node_scalars @ W_in_s
__device__ float g_v [NN * 48];    // v[n][w][c]
__device__ float g_as[NN * 32];    // scalar accumulator
__device__ float g_av[NN * 144];   // vector accumulator [n][(p*3+c)][u(16)]
__device__ float g_w [(size_t)NE * 80];  // per-edge MLP outputs [e][p(5)][u(16)]

// ---------------- f32x2 packed-math helpers (sm_103a FFMA2) ----------------
typedef unsigned long long ull;

__device__ __forceinline__ ull pack2(float x, float y) {
    ull r; asm("mov.b64 %0, {%1, %2};" : "=l"(r) : "f"(x), "f"(y)); return r;
}
__device__ __forceinline__ void unpack2(ull v, float& x, float& y) {
    asm("mov.b64 {%0, %1}, %2;" : "=f"(x), "=f"(y) : "l"(v));
}
__device__ __forceinline__ ull ffma2(ull a, ull b, ull c) {
    ull d; asm("fma.rn.f32x2 %0, %1, %2, %3;" : "=l"(d) : "l"(a), "l"(b), "l"(c));
    return d;
}
__device__ __forceinline__ void lds_v2u64(unsigned int addr, ull& a, ull& b) {
    asm volatile("ld.shared.v2.u64 {%0, %1}, [%2];"
                 : "=l"(a), "=l"(b) : "r"(addr));
}
// pack two f32 into bf16x2 (lo = first arg, hi = second arg)
__device__ __forceinline__ unsigned int bf16x2(float lo, float hi) {
    unsigned int r;
    asm("cvt.rn.bf16x2.f32 %0, %1, %2;" : "=r"(r) : "f"(hi), "f"(lo));
    return r;
}
__device__ __forceinline__ void mma_bf16(
    float& c0, float& c1, float& c2, float& c3,
    unsigned int a0, unsigned int a1, unsigned int a2, unsigned int a3,
    unsigned int b0, unsigned int b1)
{
    asm volatile(
        "mma.sync.aligned.m16n8k16.row.col.f32.bf16.bf16.f32 "
        "{%0,%1,%2,%3}, {%4,%5,%6,%7}, {%8,%9}, {%0,%1,%2,%3};"
        : "+f"(c0), "+f"(c1), "+f"(c2), "+f"(c3)
        : "r"(a0), "r"(a1), "r"(a2), "r"(a3), "r"(b0), "r"(b1));
}

// ======================= kernel Z: zero accumulators ======================
__global__ void __launch_bounds__(256) zero_kernel()
{
    int i = blockIdx.x * blockDim.x + threadIdx.x;
    float4 z = make_float4(0.f, 0.f, 0.f, 0.f);
    if (i < NN * 36) ((float4*)g_av)[i] = z;
    if (i < NN * 8)  ((float4*)g_as)[i] = z;
}

// ======================= kernel A: node pre (2 threads / node) ============
__global__ void __launch_bounds__(256) pre_kernel(
    const float* __restrict__ node_scalars,
    const float* __restrict__ node_vectors,
    const float* __restrict__ W_in_s,
    const float* __restrict__ W_in_v)
{
    __shared__ __align__(16) float sWs[16 * 16];
    __shared__ __align__(16) float sWv[16 * 16];
    for (int i = threadIdx.x; i < 256; i += blockDim.x) {
        sWs[i] = W_in_s[i];
        sWv[i] = W_in_v[i];
    }
    __syncthreads();

    int t = blockIdx.x * blockDim.x + threadIdx.x;
    int n = t >> 1;
    int h = t & 1;
    if (n >= NN) return;

    unsigned int wsb = (unsigned int)__cvta_generic_to_shared(sWs) + h * 32;
    unsigned int wvb = (unsigned int)__cvta_generic_to_shared(sWv) + h * 32;

    float nsv[16];
    {
        const float4* p = (const float4*)(node_scalars + (size_t)n * 16);
#pragma unroll
        for (int k = 0; k < 4; k++) {
            float4 q = p[k];
            nsv[4*k+0]=q.x; nsv[4*k+1]=q.y; nsv[4*k+2]=q.z; nsv[4*k+3]=q.w;
        }
    }
    float vin[48];
    {
        const float4* p = (const float4*)(node_vectors + (size_t)n * 48);
#pragma unroll
        for (int k = 0; k < 12; k++) {
            float4 q = p[k];
            vin[4*k+0]=q.x; vin[4*k+1]=q.y; vin[4*k+2]=q.z; vin[4*k+3]=q.w;
        }
    }

    ull sacc2[4];
#pragma unroll
    for (int q = 0; q < 4; q++) sacc2[q] = 0ull;
    ull vacc2[3][4];
#pragma unroll
    for (int c = 0; c < 3; c++)
#pragma unroll
        for (int q = 0; q < 4; q++) vacc2[c][q] = 0ull;

#pragma unroll 4
    for (int u = 0; u < 16; u++) {
        ull w0, w1;
        lds_v2u64(wsb + u * 64,      w0, w1);
        ull w2, w3;
        lds_v2u64(wsb + u * 64 + 16, w2, w3);
        ull aa = pack2(nsv[u], nsv[u]);
        sacc2[0] = ffma2(aa, w0, sacc2[0]);
        sacc2[1] = ffma2(aa, w1, sacc2[1]);
        sacc2[2] = ffma2(aa, w2, sacc2[2]);
        sacc2[3] = ffma2(aa, w3, sacc2[3]);

        ull v0, v1, v2, v3;
        lds_v2u64(wvb + u * 64,      v0, v1);
        lds_v2u64(wvb + u * 64 + 16, v2, v3);
#pragma unroll
        for (int c = 0; c < 3; c++) {
            ull mm = pack2(vin[u*3+c], vin[u*3+c]);
            vacc2[c][0] = ffma2(mm, v0, vacc2[c][0]);
            vacc2[c][1] = ffma2(mm, v1, vacc2[c][1]);
            vacc2[c][2] = ffma2(mm, v2, vacc2[c][2]);
            vacc2[c][3] = ffma2(mm, v3, vacc2[c][3]);
        }
    }

    {
        float s8[8];
#pragma unroll
        for (int q = 0; q < 4; q++) unpack2(sacc2[q], s8[2*q], s8[2*q+1]);
        float4* p = (float4*)(g_s + (size_t)n * 16 + 8*h);
        p[0] = make_float4(s8[0], s8[1], s8[2], s8[3]);
        p[1] = make_float4(s8[4], s8[5], s8[6], s8[7]);
    }
    {
        float vv[3][8];
#pragma unroll
        for (int c = 0; c < 3; c++)
#pragma unroll
            for (int q = 0; q < 4; q++) unpack2(vacc2[c][q], vv[c][2*q], vv[c][2*q+1]);
        float out24[24];
#pragma unroll
        for (int w = 0; w < 8; w++) {
            out24[3*w+0] = vv[0][w];
            out24[3*w+1] = vv[1][w];
            out24[3*w+2] = vv[2][w];
        }
        float4* p = (float4*)(g_v + (size_t)n * 48 + 24*h);
#pragma unroll
        for (int k = 0; k < 6; k++)
            p[k] = make_float4(out24[4*k], out24[4*k+1], out24[4*k+2], out24[4*k+3]);
    }
}

// ======================= kernel B1: radial MLP (bf16 tensor-core) =========
// Block = 64 edges. Phase 1: h = silu(emb@W1+b1) in fp32, stored bf16x2 in smem
// (double-buffered). Phase 2: w = h @ W2 via mma.m16n8k16 bf16.
// ONE __syncthreads per tile: a thread can only reach p1(t+2) after passing the
// sync in tile t+1, which requires all threads to have finished p2(t) — so
// buffer parity reuse is safe.
#define SH_STRIDE 36  // uints; A-load bank = 4g+tg -> conflict-free
#define SB_STRIDE 88  // uints; B-load bank = 24tg+g -> conflict-free
__global__ void __launch_bounds__(256) mlp_kernel(
    const float* __restrict__ radial_emb,
    const float* __restrict__ mlp_w1,
    const float* __restrict__ mlp_b1,
    const float* __restrict__ mlp_w2)
{
    __shared__ __align__(16) float sW1[8 * 64];
    __shared__ __align__(16) float sb1[64];
    __shared__ __align__(16) unsigned int sB[32 * SB_STRIDE];      // W2 bf16x2
    __shared__ __align__(16) unsigned int sH[2][64 * SH_STRIDE];   // h bf16x2, double-buffered

    for (int i = threadIdx.x; i < 8 * 64; i += blockDim.x) sW1[i] = mlp_w1[i];
    for (int i = threadIdx.x; i < 64; i += blockDim.x)     sb1[i] = mlp_b1[i];
    for (int i = threadIdx.x; i < 32 * 80; i += blockDim.x) {
        int jp = i / 80, n = i % 80;
        sB[jp * SB_STRIDE + n] = bf16x2(mlp_w2[(2*jp) * 80 + n],
                                        mlp_w2[(2*jp + 1) * 80 + n]);
    }
    __syncthreads();

    int lane = threadIdx.x & 31;
    int warp = threadIdx.x >> 5;
    int g  = lane >> 2;          // group id 0..7
    int tg = lane & 3;           // thread-in-group 0..3
    int eg   = warp >> 1;        // edge group 0..3 (16 edges each)
    int half = warp & 1;         // N-half: cols [40h, 40h+40)

    int edge_q = threadIdx.x >> 2;        // 0..63 (phase-1 edge)
    int jq     = (threadIdx.x & 3) * 16;  // phase-1 j range

    int par = 0;
    for (int tile = blockIdx.x; tile < NT; tile += gridDim.x) {
        int e0 = tile * 64;
        unsigned int* sHp = sH[par];

        // ---- phase 1: layer 1 + silu (fp32 exact), write bf16x2 h ----
        {
            const float4* pe = (const float4*)(radial_emb + (size_t)(e0 + edge_q) * 8);
            float4 ea = pe[0], eb = pe[1];
            float em[8] = {ea.x, ea.y, ea.z, ea.w, eb.x, eb.y, eb.z, eb.w};
#pragma unroll
            for (int k = 0; k < 4; k++) {
                float4 acc = *(const float4*)(sb1 + jq + 4*k);
#pragma unroll
                for (int i = 0; i < 8; i++) {
                    float4 wv = *(const float4*)(sW1 + i * 64 + jq + 4*k);
                    acc.x += em[i] * wv.x;
                    acc.y += em[i] * wv.y;
                    acc.z += em[i] * wv.z;
                    acc.w += em[i] * wv.w;
                }
                float s0 = __fdividef(acc.x, 1.f + __expf(-acc.x));
                float s1 = __fdividef(acc.y, 1.f + __expf(-acc.y));
                float s2 = __fdividef(acc.z, 1.f + __expf(-acc.z));
                float s3 = __fdividef(acc.w, 1.f + __expf(-acc.w));
                uint2 uu;
                uu.x = bf16x2(s0, s1);
                uu.y = bf16x2(s2, s3);
                *(uint2*)(sHp + edge_q * SH_STRIDE + jq / 2 + 2*k) = uu;
            }
        }
        __syncthreads();

        // ---- phase 2: layer 2 GEMM via bf16 MMA (K=16 per inst, 4 iters) ----
        float c[5][4];
#pragma unroll
        for (int nn = 0; nn < 5; nn++)
#pragma unroll
            for (int q = 0; q < 4; q++) c[nn][q] = 0.f;

        const unsigned int* h0 = sHp + (eg * 16 + g) * SH_STRIDE;
        const unsigned int* h1 = h0 + 8 * SH_STRIDE;
#pragma unroll
        for (int kk = 0; kk < 4; kk++) {
            unsigned int a0 = h0[kk*8 + tg];
            unsigned int a1 = h1[kk*8 + tg];
            unsigned int a2 = h0[kk*8 + tg + 4];
            unsigned int a3 = h1[kk*8 + tg + 4];
            const unsigned int* b0p = sB + (kk*8 + tg)     * SB_STRIDE + half * 40 + g;
            const unsigned int* b1p = sB + (kk*8 + tg + 4) * SB_STRIDE + half * 40 + g;
#pragma unroll
            for (int nn = 0; nn < 5; nn++) {
                mma_bf16(c[nn][0], c[nn][1], c[nn][2], c[nn][3],
                         a0, a1, a2, a3, b0p[nn*8], b1p[nn*8]);
            }
        }

        // ---- store: c0,c1 -> (row g, cols 2t,2t+1); c2,c3 -> row g+8 ----
        {
            int er = e0 + eg * 16 + g;
            float* w0 = g_w + (size_t)er * 80 + half * 40 + 2 * tg;
            float* w1 = g_w + (size_t)(er + 8) * 80 + half * 40 + 2 * tg;
#pragma unroll
            for (int nn = 0; nn < 5; nn++) {
                *(float2*)(w0 + nn * 8) = make_float2(c[nn][0], c[nn][1]);
                *(float2*)(w1 + nn * 8) = make_float2(c[nn][2], c[nn][3]);
            }
        }
        par ^= 1;   // no trailing sync — next tile writes the other buffer
    }
}

// ======================= kernel B2: messages + scatter (4 threads / edge) =
__global__ void __launch_bounds__(256) scatter_kernel(
    const float* __restrict__ edge_sh,
    const int*   __restrict__ senders,
    const int*   __restrict__ receivers)
{
    int t = blockIdx.x * blockDim.x + threadIdx.x;
    int e = t >> 2;
    int q = t & 3;           // u-chunk: u in [4q, 4q+4)
    if (e >= NE) return;

    const float* wp = g_w + (size_t)e * 80 + 4 * q;
    float4 w0 = *(const float4*)(wp);
    float4 w1 = *(const float4*)(wp + 16);
    float4 w2 = *(const float4*)(wp + 32);
    float4 w3 = *(const float4*)(wp + 48);
    float4 w4 = *(const float4*)(wp + 64);
    float p0[4] = {w0.x, w0.y, w0.z, w0.w};
    float p1[4] = {w1.x, w1.y, w1.z, w1.w};
    float p2[4] = {w2.x, w2.y, w2.z, w2.w};
    float p3[4] = {w3.x, w3.y, w3.z, w3.w};
    float p4[4] = {w4.x, w4.y, w4.z, w4.w};

    int snd = senders[e];
    int rcv = receivers[e];
    float4 sh4 = *(const float4*)(edge_sh + (size_t)e * 4);
    float Y0 = sh4.x, Yx = sh4.y, Yy = sh4.z, Yz = sh4.w;

    float4 xs4 = ((const float4*)(g_s + (size_t)snd * 16))[q];
    float xs[4] = {xs4.x, xs4.y, xs4.z, xs4.w};
    float xv[12];
    {
        const float4* pv = (const float4*)(g_v + (size_t)snd * 48);
        float4 q0 = pv[3*q+0], q1 = pv[3*q+1], q2 = pv[3*q+2];
        xv[0]=q0.x; xv[1]=q0.y; xv[2]=q0.z; xv[3]=q0.w;
        xv[4]=q1.x; xv[5]=q1.y; xv[6]=q1.z; xv[7]=q1.w;
        xv[8]=q2.x; xv[9]=q2.y; xv[10]=q2.z; xv[11]=q2.w;
    }

    float ms1[4], ms2[4], v1m[3][4], v2m[3][4], v3m[3][4];
#pragma unroll
    for (int i = 0; i < 4; i++) {
        float ax = xv[3*i+0], ay = xv[3*i+1], az = xv[3*i+2];
        float xsu = xs[i];
        ms1[i] = p0[i] * xsu * Y0;
        ms2[i] = p1[i] * (ax*Yx + ay*Yy + az*Yz);
        float al = p2[i] * xsu;
        v1m[0][i] = al * Yx; v1m[1][i] = al * Yy; v1m[2][i] = al * Yz;
        float be = p3[i] * Y0;
        v2m[0][i] = be * ax; v2m[1][i] = be * ay; v2m[2][i] = be * az;
        float ga = p4[i];
        v3m[0][i] = ga * (ay*Yz - az*Yy);
        v3m[1][i] = ga * (az*Yx - ax*Yz);
        v3m[2][i] = ga * (ax*Yy - ay*Yx);
    }

    float* as_base = g_as + (size_t)rcv * 32;
    float* av_base = g_av + (size_t)rcv * 144;
    atomicAdd((float4*)(as_base + 4*q),
              make_float4(ms1[0], ms1[1], ms1[2], ms1[3]));
    atomicAdd((float4*)(as_base + 16 + 4*q),
              make_float4(ms2[0], ms2[1], ms2[2], ms2[3]));
#pragma unroll
    for (int c = 0; c < 3; c++) {
        atomicAdd((float4*)(av_base + (0*3 + c) * 16 + 4*q),
                  make_float4(v1m[c][0], v1m[c][1], v1m[c][2], v1m[c][3]));
        atomicAdd((float4*)(av_base + (1*3 + c) * 16 + 4*q),
                  make_float4(v2m[c][0], v2m[c][1], v2m[c][2], v2m[c][3]));
        atomicAdd((float4*)(av_base + (2*3 + c) * 16 + 4*q),
                  make_float4(v3m[c][0], v3m[c][1], v3m[c][2], v3m[c][3]));
    }
}

// ======================= kernel C: node post (2 threads / node) ===========
__global__ void __launch_bounds__(256) post_kernel(
    const float* __restrict__ node_scalars,
    const float* __restrict__ node_vectors,
    const int*   __restrict__ species,
    const float* __restrict__ W_out_s,   // [32][32]
    const float* __restrict__ W_out_v,   // [48][16]
    const float* __restrict__ sc_s,      // [4][16][32]
    const float* __restrict__ sc_v,      // [4][16][16]
    float* __restrict__ out)             // [NN][64]
{
    __shared__ __align__(16) float sWs [32 * 32];
    __shared__ __align__(16) float sWv [48 * 16];
    __shared__ __align__(16) float sScs[4 * 16 * 32];
    __shared__ __align__(16) float sScv[4 * 16 * 16];
    for (int i = threadIdx.x; i < 32*32; i += blockDim.x) sWs[i] = W_out_s[i];
    for (int i = threadIdx.x; i < 48*16; i += blockDim.x) sWv[i] = W_out_v[i];
    for (int i = threadIdx.x; i < 4*16*32; i += blockDim.x) sScs[i] = sc_s[i];
    for (int i = threadIdx.x; i < 4*16*16; i += blockDim.x) sScv[i] = sc_v[i];
    __syncthreads();

    int t = blockIdx.x * blockDim.x + threadIdx.x;
    int n = t >> 1;
    int h = t & 1;
    if (n >= NN) return;

    int sp = species[n];

    unsigned int wsb  = (unsigned int)__cvta_generic_to_shared(sWs)  + h * 32;
    unsigned int wvb  = (unsigned int)__cvta_generic_to_shared(sWv)  + h * 32;
    unsigned int scsb = (unsigned int)__cvta_generic_to_shared(sScs) + sp * 2048 + h * 32;
    unsigned int scvb = (unsigned int)__cvta_generic_to_shared(sScv) + sp * 1024 + h * 32;

    ull psa[4], psg[4];
#pragma unroll
    for (int q = 0; q < 4; q++) { psa[q] = 0ull; psg[q] = 0ull; }

    {
        float asv[32];
        const float4* p = (const float4*)(g_as + (size_t)n * 32);
#pragma unroll
        for (int k = 0; k < 8; k++) {
            float4 q = p[k];
            asv[4*k+0]=q.x; asv[4*k+1]=q.y; asv[4*k+2]=q.z; asv[4*k+3]=q.w;
        }
#pragma unroll 4
        for (int k = 0; k < 32; k++) {
            float a = asv[k] * INV_SQRT_DEG;
            ull aa = pack2(a, a);
            ull r0, r1, r2, r3;
            lds_v2u64(wsb + k * 128,      r0, r1);
            lds_v2u64(wsb + k * 128 + 64, r2, r3);
            psa[0] = ffma2(aa, r0, psa[0]);
            psa[1] = ffma2(aa, r1, psa[1]);
            psg[0] = ffma2(aa, r2, psg[0]);
            psg[1] = ffma2(aa, r3, psg[1]);
            lds_v2u64(wsb + k * 128 + 16, r0, r1);
            lds_v2u64(wsb + k * 128 + 80, r2, r3);
            psa[2] = ffma2(aa, r0, psa[2]);
            psa[3] = ffma2(aa, r1, psa[3]);
            psg[2] = ffma2(aa, r2, psg[2]);
            psg[3] = ffma2(aa, r3, psg[3]);
        }
    }

    float nsv[16];
    {
        const float4* p = (const float4*)(node_scalars + (size_t)n * 16);
#pragma unroll
        for (int k = 0; k < 4; k++) {
            float4 q = p[k];
            nsv[4*k+0]=q.x; nsv[4*k+1]=q.y; nsv[4*k+2]=q.z; nsv[4*k+3]=q.w;
        }
    }
#pragma unroll 4
    for (int u = 0; u < 16; u++) {
        ull aa = pack2(nsv[u], nsv[u]);
        ull r0, r1, r2, r3;
        lds_v2u64(scsb + u * 128,      r0, r1);
        lds_v2u64(scsb + u * 128 + 64, r2, r3);
        psa[0] = ffma2(aa, r0, psa[0]);
        psa[1] = ffma2(aa, r1, psa[1]);
        psg[0] = ffma2(aa, r2, psg[0]);
        psg[1] = ffma2(aa, r3, psg[1]);
        lds_v2u64(scsb + u * 128 + 16, r0, r1);
        lds_v2u64(scsb + u * 128 + 80, r2, r3);
        psa[2] = ffma2(aa, r0, psa[2]);
        psa[3] = ffma2(aa, r1, psa[3]);
        psg[2] = ffma2(aa, r2, psg[2]);
        psg[3] = ffma2(aa, r3, psg[3]);
    }

    ull pv2[3][4];
#pragma unroll
    for (int c = 0; c < 3; c++)
#pragma unroll
        for (int q = 0; q < 4; q++) pv2[c][q] = 0ull;

    const float* av = g_av + (size_t)n * 144;
#pragma unroll
    for (int p = 0; p < 3; p++) {
        float m0[16], m1[16], m2[16];
        {
            const float4* q0 = (const float4*)(av + (p*3+0)*16);
            const float4* q1 = (const float4*)(av + (p*3+1)*16);
            const float4* q2 = (const float4*)(av + (p*3+2)*16);
#pragma unroll
            for (int k = 0; k < 4; k++) {
                float4 a = q0[k]; m0[4*k]=a.x; m0[4*k+1]=a.y; m0[4*k+2]=a.z; m0[4*k+3]=a.w;
                float4 b = q1[k]; m1[4*k]=b.x; m1[4*k+1]=b.y; m1[4*k+2]=b.z; m1[4*k+3]=b.w;
                float4 c4 = q2[k]; m2[4*k]=c4.x; m2[4*k+1]=c4.y; m2[4*k+2]=c4.z; m2[4*k+3]=c4.w;
            }
        }
#pragma unroll 4
        for (int u = 0; u < 16; u++) {
            ull r0, r1, r2, r3;
            lds_v2u64(wvb + (p*16 + u) * 64,      r0, r1);
            lds_v2u64(wvb + (p*16 + u) * 64 + 16, r2, r3);
            ull mm0 = pack2(m0[u]*INV_SQRT_DEG, m0[u]*INV_SQRT_DEG);
            ull mm1 = pack2(m1[u]*INV_SQRT_DEG, m1[u]*INV_SQRT_DEG);
            ull mm2 = pack2(m2[u]*INV_SQRT_DEG, m2[u]*INV_SQRT_DEG);
            pv2[0][0] = ffma2(mm0, r0, pv2[0][0]);
            pv2[0][1] = ffma2(mm0, r1, pv2[0][1]);
            pv2[0][2] = ffma2(mm0, r2, pv2[0][2]);
            pv2[0][3] = ffma2(mm0, r3, pv2[0][3]);
            pv2[1][0] = ffma2(mm1, r0, pv2[1][0]);
            pv2[1][1] = ffma2(mm1, r1, pv2[1][1]);
            pv2[1][2] = ffma2(mm1, r2, pv2[1][2]);
            pv2[1][3] = ffma2(mm1, r3, pv2[1][3]);
            pv2[2][0] = ffma2(mm2, r0, pv2[2][0]);
            pv2[2][1] = ffma2(mm2, r1, pv2[2][1]);
            pv2[2][2] = ffma2(mm2, r2, pv2[2][2]);
            pv2[2][3] = ffma2(mm2, r3, pv2[2][3]);
        }
    }

    float vin[48];
    {
        const float4* p = (const float4*)(node_vectors + (size_t)n * 48);
#pragma unroll
        for (int k = 0; k < 12; k++) {
            float4 q = p[k];
            vin[4*k+0]=q.x; vin[4*k+1]=q.y; vin[4*k+2]=q.z; vin[4*k+3]=q.w;
        }
    }
#pragma unroll 4
    for (int u = 0; u < 16; u++) {
        ull r0, r1, r2, r3;
        lds_v2u64(scvb + u * 64,      r0, r1);
        lds_v2u64(scvb + u * 64 + 16, r2, r3);
        ull mm0 = pack2(vin[u*3+0], vin[u*3+0]);
        ull mm1 = pack2(vin[u*3+1], vin[u*3+1]);
        ull mm2 = pack2(vin[u*3+2], vin[u*3+2]);
        pv2[0][0] = ffma2(mm0, r0, pv2[0][0]);
        pv2[0][1] = ffma2(mm0, r1, pv2[0][1]);
        pv2[0][2] = ffma2(mm0, r2, pv2[0][2]);
        pv2[0][3] = ffma2(mm0, r3, pv2[0][3]);
        pv2[1][0] = ffma2(mm1, r0, pv2[1][0]);
        pv2[1][1] = ffma2(mm1, r1, pv2[1][1]);
        pv2[1][2] = ffma2(mm1, r2, pv2[1][2]);
        pv2[1][3] = ffma2(mm1, r3, pv2[1][3]);
        pv2[2][0] = ffma2(mm2, r0, pv2[2][0]);
        pv2[2][1] = ffma2(mm2, r1, pv2[2][1]);
        pv2[2][2] = ffma2(mm2, r2, pv2[2][2]);
        pv2[2][3] = ffma2(mm2, r3, pv2[2][3]);
    }

    float sa[8], sg[8], pvv[3][8];
#pragma unroll
    for (int q = 0; q < 4; q++) {
        unpack2(psa[q], sa[2*q], sa[2*q+1]);
        unpack2(psg[q], sg[2*q], sg[2*q+1]);
    }
#pragma unroll
    for (int c = 0; c < 3; c++)
#pragma unroll
        for (int q = 0; q < 4; q++)
            unpack2(pv2[c][q], pvv[c][2*q], pvv[c][2*q+1]);

    {
        float o8[8];
#pragma unroll
        for (int i = 0; i < 8; i++) {
            float x = sa[i];
            o8[i] = __fdividef(x, 1.f + __expf(-x)) + nsv[8*h + i];
        }
        float4* p = (float4*)(out + (size_t)n * 64 + 8*h);
        p[0] = make_float4(o8[0], o8[1], o8[2], o8[3]);
        p[1] = make_float4(o8[4], o8[5], o8[6], o8[7]);
    }
    {
        float o24[24];
#pragma unroll
        for (int i = 0; i < 8; i++) {
            float g = __fdividef(1.f, 1.f + __expf(-sg[i]));
            int w = 8*h + i;
            o24[3*i+0] = pvv[0][i] * g + vin[3*w+0];
            o24[3*i+1] = pvv[1][i] * g + vin[3*w+1];
            o24[3*i+2] = pvv[2][i] * g + vin[3*w+2];
        }
        float4* p = (float4*)(out + (size_t)n * 64 + 16 + 24*h);
#pragma unroll
        for (int k = 0; k < 6; k++)
            p[k] = make_float4(o24[4*k], o24[4*k+1], o24[4*k+2], o24[4*k+3]);
    }
}

// ======================= launcher ========================================
extern "C" void kernel_launch(void* const* d_in, const int* in_sizes, int n_in,
                              void* d_out, int out_size)
{
    const float* node_scalars = (const float*)d_in[0];
    const float* node_vectors = (const float*)d_in[1];
    const float* edge_sh      = (const float*)d_in[2];
    const float* radial_emb   = (const float*)d_in[3];
    const int*   senders      = (const int*)  d_in[4];
    const int*   receivers    = (const int*)  d_in[5];
    const int*   species      = (const int*)  d_in[6];
    const float* W_in_s       = (const float*)d_in[7];
    const float* W_in_v       = (const float*)d_in[8];
    const float* mlp_w1       = (const float*)d_in[9];
    const float* mlp_b1       = (const float*)d_in[10];
    const float* mlp_w2       = (const float*)d_in[11];
    const float* W_out_s      = (const float*)d_in[12];
    const float* W_out_v      = (const float*)d_in[13];
    const float* sc_s         = (const float*)d_in[14];
    const float* sc_v         = (const float*)d_in[15];
    float* out = (float*)d_out;

    zero_kernel<<<(NN * 36 + 255) / 256, 256>>>();
    pre_kernel<<<(2 * NN + 255) / 256, 256>>>(node_scalars, node_vectors, W_in_s, W_in_v);
    mlp_kernel<<<1480, 256>>>(radial_emb, mlp_w1, mlp_b1, mlp_w2);
    scatter_kernel<<<(4 * NE + 255) / 256, 256>>>(edge_sh, senders, receivers);
    post_kernel<<<(2 * NN + 255) / 256, 256>>>(node_scalars, node_vectors, species,
                                               W_out_s, W_out_v, sc_s, sc_v, out);
}

// round 16
// speedup vs baseline: 1.2050x; 1.1583x over previous
#include <cuda_runtime.h>
#include <cuda_bf16.h>
#include <cstdint>

#define NN 50000
#define NE 800000
#define NT 12500            // NE / 64 edge-tiles
#define INV_SQRT_DEG 0.25f  // 1/sqrt(16)

// ---------------- scratch ----------
__device__ float g_s [NN * 16];    // s = node_scalars @ W_in_s
__device__ float g_v [NN * 48];    // v[n][w][c]
__device__ float g_as[NN * 32];    // scalar accumulator
__device__ float g_av[NN * 144];   // vector accumulator [n][(p*3+c)][u(16)]

// ---------------- f32x2 packed-math helpers (sm_103a FFMA2) ----------------
typedef unsigned long long ull;

__device__ __forceinline__ ull pack2(float x, float y) {
    ull r; asm("mov.b64 %0, {%1, %2};" : "=l"(r) : "f"(x), "f"(y)); return r;
}
__device__ __forceinline__ void unpack2(ull v, float& x, float& y) {
    asm("mov.b64 {%0, %1}, %2;" : "=f"(x), "=f"(y) : "l"(v));
}
__device__ __forceinline__ ull ffma2(ull a, ull b, ull c) {
    ull d; asm("fma.rn.f32x2 %0, %1, %2, %3;" : "=l"(d) : "l"(a), "l"(b), "l"(c));
    return d;
}
__device__ __forceinline__ void lds_v2u64(unsigned int addr, ull& a, ull& b) {
    asm volatile("ld.shared.v2.u64 {%0, %1}, [%2];"
                 : "=l"(a), "=l"(b) : "r"(addr));
}
// pack two f32 into bf16x2 (lo = first arg, hi = second arg)
__device__ __forceinline__ unsigned int bf16x2(float lo, float hi) {
    unsigned int r;
    asm("cvt.rn.bf16x2.f32 %0, %1, %2;" : "=r"(r) : "f"(hi), "f"(lo));
    return r;
}
__device__ __forceinline__ void mma_bf16(
    float& c0, float& c1, float& c2, float& c3,
    unsigned int a0, unsigned int a1, unsigned int a2, unsigned int a3,
    unsigned int b0, unsigned int b1)
{
    asm volatile(
        "mma.sync.aligned.m16n8k16.row.col.f32.bf16.bf16.f32 "
        "{%0,%1,%2,%3}, {%4,%5,%6,%7}, {%8,%9}, {%0,%1,%2,%3};"
        : "+f"(c0), "+f"(c1), "+f"(c2), "+f"(c3)
        : "r"(a0), "r"(a1), "r"(a2), "r"(a3), "r"(b0), "r"(b1));
}

// ======================= kernel Z: zero accumulators ======================
__global__ void __launch_bounds__(256) zero_kernel()
{
    int i = blockIdx.x * blockDim.x + threadIdx.x;
    float4 z = make_float4(0.f, 0.f, 0.f, 0.f);
    if (i < NN * 36) ((float4*)g_av)[i] = z;
    if (i < NN * 8)  ((float4*)g_as)[i] = z;
}

// ======================= kernel A: node pre (2 threads / node) ============
__global__ void __launch_bounds__(256) pre_kernel(
    const float* __restrict__ node_scalars,
    const float* __restrict__ node_vectors,
    const float* __restrict__ W_in_s,
    const float* __restrict__ W_in_v)
{
    __shared__ __align__(16) float sWs[16 * 16];
    __shared__ __align__(16) float sWv[16 * 16];
    for (int i = threadIdx.x; i < 256; i += blockDim.x) {
        sWs[i] = W_in_s[i];
        sWv[i] = W_in_v[i];
    }
    __syncthreads();

    int t = blockIdx.x * blockDim.x + threadIdx.x;
    int n = t >> 1;
    int h = t & 1;
    if (n >= NN) return;

    unsigned int wsb = (unsigned int)__cvta_generic_to_shared(sWs) + h * 32;
    unsigned int wvb = (unsigned int)__cvta_generic_to_shared(sWv) + h * 32;

    float nsv[16];
    {
        const float4* p = (const float4*)(node_scalars + (size_t)n * 16);
#pragma unroll
        for (int k = 0; k < 4; k++) {
            float4 q = p[k];
            nsv[4*k+0]=q.x; nsv[4*k+1]=q.y; nsv[4*k+2]=q.z; nsv[4*k+3]=q.w;
        }
    }
    float vin[48];
    {
        const float4* p = (const float4*)(node_vectors + (size_t)n * 48);
#pragma unroll
        for (int k = 0; k < 12; k++) {
            float4 q = p[k];
            vin[4*k+0]=q.x; vin[4*k+1]=q.y; vin[4*k+2]=q.z; vin[4*k+3]=q.w;
        }
    }

    ull sacc2[4];
#pragma unroll
    for (int q = 0; q < 4; q++) sacc2[q] = 0ull;
    ull vacc2[3][4];
#pragma unroll
    for (int c = 0; c < 3; c++)
#pragma unroll
        for (int q = 0; q < 4; q++) vacc2[c][q] = 0ull;

#pragma unroll 4
    for (int u = 0; u < 16; u++) {
        ull w0, w1;
        lds_v2u64(wsb + u * 64,      w0, w1);
        ull w2, w3;
        lds_v2u64(wsb + u * 64 + 16, w2, w3);
        ull aa = pack2(nsv[u], nsv[u]);
        sacc2[0] = ffma2(aa, w0, sacc2[0]);
        sacc2[1] = ffma2(aa, w1, sacc2[1]);
        sacc2[2] = ffma2(aa, w2, sacc2[2]);
        sacc2[3] = ffma2(aa, w3, sacc2[3]);

        ull v0, v1, v2, v3;
        lds_v2u64(wvb + u * 64,      v0, v1);
        lds_v2u64(wvb + u * 64 + 16, v2, v3);
#pragma unroll
        for (int c = 0; c < 3; c++) {
            ull mm = pack2(vin[u*3+c], vin[u*3+c]);
            vacc2[c][0] = ffma2(mm, v0, vacc2[c][0]);
            vacc2[c][1] = ffma2(mm, v1, vacc2[c][1]);
            vacc2[c][2] = ffma2(mm, v2, vacc2[c][2]);
            vacc2[c][3] = ffma2(mm, v3, vacc2[c][3]);
        }
    }

    {
        float s8[8];
#pragma unroll
        for (int q = 0; q < 4; q++) unpack2(sacc2[q], s8[2*q], s8[2*q+1]);
        float4* p = (float4*)(g_s + (size_t)n * 16 + 8*h);
        p[0] = make_float4(s8[0], s8[1], s8[2], s8[3]);
        p[1] = make_float4(s8[4], s8[5], s8[6], s8[7]);
    }
    {
        float vv[3][8];
#pragma unroll
        for (int c = 0; c < 3; c++)
#pragma unroll
            for (int q = 0; q < 4; q++) unpack2(vacc2[c][q], vv[c][2*q], vv[c][2*q+1]);
        float out24[24];
#pragma unroll
        for (int w = 0; w < 8; w++) {
            out24[3*w+0] = vv[0][w];
            out24[3*w+1] = vv[1][w];
            out24[3*w+2] = vv[2][w];
        }
        float4* p = (float4*)(g_v + (size_t)n * 48 + 24*h);
#pragma unroll
        for (int k = 0; k < 6; k++)
            p[k] = make_float4(out24[4*k], out24[4*k+1], out24[4*k+2], out24[4*k+3]);
    }
}

// ======================= kernel B: fused MLP + scatter ====================
// Block = 64 edges per tile (persistent, grid-strided).
//   phase 1: h = silu(emb@W1+b1) fp32 -> bf16x2 sH       (sync A)
//   phase 2: w = h @ W2 via bf16 MMA -> fp32 sWst (smem)  (sync B)
//   phase 3: scatter — thread t = (edge t>>2, chunk t&3): read 20 floats
//            from sWst, gather sender data, 11x RED.128 atomics.
// Sync-A of tile t+1 guarantees scatter(t) done before phase-2(t+1)
// overwrites sWst, and phase-2(t) reads of sH done before phase-1(t+1).
#define SH_STRIDE 36   // uints
#define SB_STRIDE 88   // uints
#define SW_STRIDE 84   // floats per edge row in staging
__global__ void __launch_bounds__(256) edge_fused_kernel(
    const float* __restrict__ radial_emb,
    const float* __restrict__ mlp_w1,
    const float* __restrict__ mlp_b1,
    const float* __restrict__ mlp_w2,
    const float* __restrict__ edge_sh,
    const int*   __restrict__ senders,
    const int*   __restrict__ receivers)
{
    __shared__ __align__(16) float sW1[8 * 64];
    __shared__ __align__(16) float sb1[64];
    __shared__ __align__(16) unsigned int sB[32 * SB_STRIDE];   // W2 bf16x2
    __shared__ __align__(16) unsigned int sH[64 * SH_STRIDE];   // h bf16x2
    __shared__ __align__(16) float sWst[64 * SW_STRIDE];        // fp32 staging

    for (int i = threadIdx.x; i < 8 * 64; i += blockDim.x) sW1[i] = mlp_w1[i];
    for (int i = threadIdx.x; i < 64; i += blockDim.x)     sb1[i] = mlp_b1[i];
    for (int i = threadIdx.x; i < 32 * 80; i += blockDim.x) {
        int jp = i / 80, n = i % 80;
        sB[jp * SB_STRIDE + n] = bf16x2(mlp_w2[(2*jp) * 80 + n],
                                        mlp_w2[(2*jp + 1) * 80 + n]);
    }
    __syncthreads();

    int lane = threadIdx.x & 31;
    int warp = threadIdx.x >> 5;
    int g  = lane >> 2;          // group id 0..7
    int tg = lane & 3;           // thread-in-group 0..3
    int eg   = warp >> 1;        // edge group 0..3 (16 edges each)
    int half = warp & 1;         // N-half: cols [40h, 40h+40)

    int edge_q = threadIdx.x >> 2;        // 0..63 (phase-1 edge / phase-3 edge)
    int jq     = (threadIdx.x & 3) * 16;  // phase-1 j range
    int qc     = threadIdx.x & 3;         // phase-3 u-chunk

    for (int tile = blockIdx.x; tile < NT; tile += gridDim.x) {
        int e0 = tile * 64;

        // ---- phase 1: layer 1 + silu (fp32 exact), write bf16x2 h ----
        {
            const float4* pe = (const float4*)(radial_emb + (size_t)(e0 + edge_q) * 8);
            float4 ea = pe[0], eb = pe[1];
            float em[8] = {ea.x, ea.y, ea.z, ea.w, eb.x, eb.y, eb.z, eb.w};
#pragma unroll
            for (int k = 0; k < 4; k++) {
                float4 acc = *(const float4*)(sb1 + jq + 4*k);
#pragma unroll
                for (int i = 0; i < 8; i++) {
                    float4 wv = *(const float4*)(sW1 + i * 64 + jq + 4*k);
                    acc.x += em[i] * wv.x;
                    acc.y += em[i] * wv.y;
                    acc.z += em[i] * wv.z;
                    acc.w += em[i] * wv.w;
                }
                float s0 = __fdividef(acc.x, 1.f + __expf(-acc.x));
                float s1 = __fdividef(acc.y, 1.f + __expf(-acc.y));
                float s2 = __fdividef(acc.z, 1.f + __expf(-acc.z));
                float s3 = __fdividef(acc.w, 1.f + __expf(-acc.w));
                uint2 uu;
                uu.x = bf16x2(s0, s1);
                uu.y = bf16x2(s2, s3);
                *(uint2*)(sH + edge_q * SH_STRIDE + jq / 2 + 2*k) = uu;
            }
        }
        __syncthreads();   // sync A

        // ---- phase 2: layer 2 GEMM via bf16 MMA, stage fp32 to smem ----
        {
            float c[5][4];
#pragma unroll
            for (int nn = 0; nn < 5; nn++)
#pragma unroll
                for (int q = 0; q < 4; q++) c[nn][q] = 0.f;

            const unsigned int* h0 = sH + (eg * 16 + g) * SH_STRIDE;
            const unsigned int* h1 = h0 + 8 * SH_STRIDE;
#pragma unroll
            for (int kk = 0; kk < 4; kk++) {
                unsigned int a0 = h0[kk*8 + tg];
                unsigned int a1 = h1[kk*8 + tg];
                unsigned int a2 = h0[kk*8 + tg + 4];
                unsigned int a3 = h1[kk*8 + tg + 4];
                const unsigned int* b0p = sB + (kk*8 + tg)     * SB_STRIDE + half * 40 + g;
                const unsigned int* b1p = sB + (kk*8 + tg + 4) * SB_STRIDE + half * 40 + g;
#pragma unroll
                for (int nn = 0; nn < 5; nn++) {
                    mma_bf16(c[nn][0], c[nn][1], c[nn][2], c[nn][3],
                             a0, a1, a2, a3, b0p[nn*8], b1p[nn*8]);
                }
            }
            // stage: rows (eg*16+g) and (eg*16+g+8)
            float* w0 = sWst + (eg * 16 + g) * SW_STRIDE + half * 40 + 2 * tg;
            float* w1 = w0 + 8 * SW_STRIDE;
#pragma unroll
            for (int nn = 0; nn < 5; nn++) {
                *(float2*)(w0 + nn * 8) = make_float2(c[nn][0], c[nn][1]);
                *(float2*)(w1 + nn * 8) = make_float2(c[nn][2], c[nn][3]);
            }
        }
        __syncthreads();   // sync B

        // ---- phase 3: messages + scatter (thread -> edge edge_q, chunk qc) --
        {
            int e = e0 + edge_q;
            const float* wp = sWst + edge_q * SW_STRIDE + 4 * qc;
            float4 w0 = *(const float4*)(wp);
            float4 w1 = *(const float4*)(wp + 16);
            float4 w2 = *(const float4*)(wp + 32);
            float4 w3 = *(const float4*)(wp + 48);
            float4 w4 = *(const float4*)(wp + 64);
            float p0[4] = {w0.x, w0.y, w0.z, w0.w};
            float p1[4] = {w1.x, w1.y, w1.z, w1.w};
            float p2[4] = {w2.x, w2.y, w2.z, w2.w};
            float p3[4] = {w3.x, w3.y, w3.z, w3.w};
            float p4[4] = {w4.x, w4.y, w4.z, w4.w};

            int snd = senders[e];
            int rcv = receivers[e];
            float4 sh4 = *(const float4*)(edge_sh + (size_t)e * 4);
            float Y0 = sh4.x, Yx = sh4.y, Yy = sh4.z, Yz = sh4.w;

            float4 xs4 = ((const float4*)(g_s + (size_t)snd * 16))[qc];
            float xs[4] = {xs4.x, xs4.y, xs4.z, xs4.w};
            float xv[12];
            {
                const float4* pv = (const float4*)(g_v + (size_t)snd * 48);
                float4 q0 = pv[3*qc+0], q1 = pv[3*qc+1], q2 = pv[3*qc+2];
                xv[0]=q0.x; xv[1]=q0.y; xv[2]=q0.z; xv[3]=q0.w;
                xv[4]=q1.x; xv[5]=q1.y; xv[6]=q1.z; xv[7]=q1.w;
                xv[8]=q2.x; xv[9]=q2.y; xv[10]=q2.z; xv[11]=q2.w;
            }

            float ms1[4], ms2[4], v1m[3][4], v2m[3][4], v3m[3][4];
#pragma unroll
            for (int i = 0; i < 4; i++) {
                float ax = xv[3*i+0], ay = xv[3*i+1], az = xv[3*i+2];
                float xsu = xs[i];
                ms1[i] = p0[i] * xsu * Y0;
                ms2[i] = p1[i] * (ax*Yx + ay*Yy + az*Yz);
                float al = p2[i] * xsu;
                v1m[0][i] = al * Yx; v1m[1][i] = al * Yy; v1m[2][i] = al * Yz;
                float be = p3[i] * Y0;
                v2m[0][i] = be * ax; v2m[1][i] = be * ay; v2m[2][i] = be * az;
                float ga = p4[i];
                v3m[0][i] = ga * (ay*Yz - az*Yy);
                v3m[1][i] = ga * (az*Yx - ax*Yz);
                v3m[2][i] = ga * (ax*Yy - ay*Yx);
            }

            float* as_base = g_as + (size_t)rcv * 32;
            float* av_base = g_av + (size_t)rcv * 144;
            atomicAdd((float4*)(as_base + 4*qc),
                      make_float4(ms1[0], ms1[1], ms1[2], ms1[3]));
            atomicAdd((float4*)(as_base + 16 + 4*qc),
                      make_float4(ms2[0], ms2[1], ms2[2], ms2[3]));
#pragma unroll
            for (int c = 0; c < 3; c++) {
                atomicAdd((float4*)(av_base + (0*3 + c) * 16 + 4*qc),
                          make_float4(v1m[c][0], v1m[c][1], v1m[c][2], v1m[c][3]));
                atomicAdd((float4*)(av_base + (1*3 + c) * 16 + 4*qc),
                          make_float4(v2m[c][0], v2m[c][1], v2m[c][2], v2m[c][3]));
                atomicAdd((float4*)(av_base + (2*3 + c) * 16 + 4*qc),
                          make_float4(v3m[c][0], v3m[c][1], v3m[c][2], v3m[c][3]));
            }
        }
        // no sync here: next tile's sync A protects sWst (phase-2 writes come
        // after it) and sH (phase-1 writes precede it on each thread's own path)
    }
}

// ======================= kernel C: node post (2 threads / node) ===========
__global__ void __launch_bounds__(256) post_kernel(
    const float* __restrict__ node_scalars,
    const float* __restrict__ node_vectors,
    const int*   __restrict__ species,
    const float* __restrict__ W_out_s,   // [32][32]
    const float* __restrict__ W_out_v,   // [48][16]
    const float* __restrict__ sc_s,      // [4][16][32]
    const float* __restrict__ sc_v,      // [4][16][16]
    float* __restrict__ out)             // [NN][64]
{
    __shared__ __align__(16) float sWs [32 * 32];
    __shared__ __align__(16) float sWv [48 * 16];
    __shared__ __align__(16) float sScs[4 * 16 * 32];
    __shared__ __align__(16) float sScv[4 * 16 * 16];
    for (int i = threadIdx.x; i < 32*32; i += blockDim.x) sWs[i] = W_out_s[i];
    for (int i = threadIdx.x; i < 48*16; i += blockDim.x) sWv[i] = W_out_v[i];
    for (int i = threadIdx.x; i < 4*16*32; i += blockDim.x) sScs[i] = sc_s[i];
    for (int i = threadIdx.x; i < 4*16*16; i += blockDim.x) sScv[i] = sc_v[i];
    __syncthreads();

    int t = blockIdx.x * blockDim.x + threadIdx.x;
    int n = t >> 1;
    int h = t & 1;
    if (n >= NN) return;

    int sp = species[n];

    unsigned int wsb  = (unsigned int)__cvta_generic_to_shared(sWs)  + h * 32;
    unsigned int wvb  = (unsigned int)__cvta_generic_to_shared(sWv)  + h * 32;
    unsigned int scsb = (unsigned int)__cvta_generic_to_shared(sScs) + sp * 2048 + h * 32;
    unsigned int scvb = (unsigned int)__cvta_generic_to_shared(sScv) + sp * 1024 + h * 32;

    ull psa[4], psg[4];
#pragma unroll
    for (int q = 0; q < 4; q++) { psa[q] = 0ull; psg[q] = 0ull; }

    {
        float asv[32];
        const float4* p = (const float4*)(g_as + (size_t)n * 32);
#pragma unroll
        for (int k = 0; k < 8; k++) {
            float4 q = p[k];
            asv[4*k+0]=q.x; asv[4*k+1]=q.y; asv[4*k+2]=q.z; asv[4*k+3]=q.w;
        }
#pragma unroll 4
        for (int k = 0; k < 32; k++) {
            float a = asv[k] * INV_SQRT_DEG;
            ull aa = pack2(a, a);
            ull r0, r1, r2, r3;
            lds_v2u64(wsb + k * 128,      r0, r1);
            lds_v2u64(wsb + k * 128 + 64, r2, r3);
            psa[0] = ffma2(aa, r0, psa[0]);
            psa[1] = ffma2(aa, r1, psa[1]);
            psg[0] = ffma2(aa, r2, psg[0]);
            psg[1] = ffma2(aa, r3, psg[1]);
            lds_v2u64(wsb + k * 128 + 16, r0, r1);
            lds_v2u64(wsb + k * 128 + 80, r2, r3);
            psa[2] = ffma2(aa, r0, psa[2]);
            psa[3] = ffma2(aa, r1, psa[3]);
            psg[2] = ffma2(aa, r2, psg[2]);
            psg[3] = ffma2(aa, r3, psg[3]);
        }
    }

    float nsv[16];
    {
        const float4* p = (const float4*)(node_scalars + (size_t)n * 16);
#pragma unroll
        for (int k = 0; k < 4; k++) {
            float4 q = p[k];
            nsv[4*k+0]=q.x; nsv[4*k+1]=q.y; nsv[4*k+2]=q.z; nsv[4*k+3]=q.w;
        }
    }
#pragma unroll 4
    for (int u = 0; u < 16; u++) {
        ull aa = pack2(nsv[u], nsv[u]);
        ull r0, r1, r2, r3;
        lds_v2u64(scsb + u * 128,      r0, r1);
        lds_v2u64(scsb + u * 128 + 64, r2, r3);
        psa[0] = ffma2(aa, r0, psa[0]);
        psa[1] = ffma2(aa, r1, psa[1]);
        psg[0] = ffma2(aa, r2, psg[0]);
        psg[1] = ffma2(aa, r3, psg[1]);
        lds_v2u64(scsb + u * 128 + 16, r0, r1);
        lds_v2u64(scsb + u * 128 + 80, r2, r3);
        psa[2] = ffma2(aa, r0, psa[2]);
        psa[3] = ffma2(aa, r1, psa[3]);
        psg[2] = ffma2(aa, r2, psg[2]);
        psg[3] = ffma2(aa, r3, psg[3]);
    }

    ull pv2[3][4];
#pragma unroll
    for (int c = 0; c < 3; c++)
#pragma unroll
        for (int q = 0; q < 4; q++) pv2[c][q] = 0ull;

    const float* av = g_av + (size_t)n * 144;
#pragma unroll
    for (int p = 0; p < 3; p++) {
        float m0[16], m1[16], m2[16];
        {
            const float4* q0 = (const float4*)(av + (p*3+0)*16);
            const float4* q1 = (const float4*)(av + (p*3+1)*16);
            const float4* q2 = (const float4*)(av + (p*3+2)*16);
#pragma unroll
            for (int k = 0; k < 4; k++) {
                float4 a = q0[k]; m0[4*k]=a.x; m0[4*k+1]=a.y; m0[4*k+2]=a.z; m0[4*k+3]=a.w;
                float4 b = q1[k]; m1[4*k]=b.x; m1[4*k+1]=b.y; m1[4*k+2]=b.z; m1[4*k+3]=b.w;
                float4 c4 = q2[k]; m2[4*k]=c4.x; m2[4*k+1]=c4.y; m2[4*k+2]=c4.z; m2[4*k+3]=c4.w;
            }
        }
#pragma unroll 4
        for (int u = 0; u < 16; u++) {
            ull r0, r1, r2, r3;
            lds_v2u64(wvb + (p*16 + u) * 64,      r0, r1);
            lds_v2u64(wvb + (p*16 + u) * 64 + 16, r2, r3);
            ull mm0 = pack2(m0[u]*INV_SQRT_DEG, m0[u]*INV_SQRT_DEG);
            ull mm1 = pack2(m1[u]*INV_SQRT_DEG, m1[u]*INV_SQRT_DEG);
            ull mm2 = pack2(m2[u]*INV_SQRT_DEG, m2[u]*INV_SQRT_DEG);
            pv2[0][0] = ffma2(mm0, r0, pv2[0][0]);
            pv2[0][1] = ffma2(mm0, r1, pv2[0][1]);
            pv2[0][2] = ffma2(mm0, r2, pv2[0][2]);
            pv2[0][3] = ffma2(mm0, r3, pv2[0][3]);
            pv2[1][0] = ffma2(mm1, r0, pv2[1][0]);
            pv2[1][1] = ffma2(mm1, r1, pv2[1][1]);
            pv2[1][2] = ffma2(mm1, r2, pv2[1][2]);
            pv2[1][3] = ffma2(mm1, r3, pv2[1][3]);
            pv2[2][0] = ffma2(mm2, r0, pv2[2][0]);
            pv2[2][1] = ffma2(mm2, r1, pv2[2][1]);
            pv2[2][2] = ffma2(mm2, r2, pv2[2][2]);
            pv2[2][3] = ffma2(mm2, r3, pv2[2][3]);
        }
    }

    float vin[48];
    {
        const float4* p = (const float4*)(node_vectors + (size_t)n * 48);
#pragma unroll
        for (int k = 0; k < 12; k++) {
            float4 q = p[k];
            vin[4*k+0]=q.x; vin[4*k+1]=q.y; vin[4*k+2]=q.z; vin[4*k+3]=q.w;
        }
    }
#pragma unroll 4
    for (int u = 0; u < 16; u++) {
        ull r0, r1, r2, r3;
        lds_v2u64(scvb + u * 64,      r0, r1);
        lds_v2u64(scvb + u * 64 + 16, r2, r3);
        ull mm0 = pack2(vin[u*3+0], vin[u*3+0]);
        ull mm1 = pack2(vin[u*3+1], vin[u*3+1]);
        ull mm2 = pack2(vin[u*3+2], vin[u*3+2]);
        pv2[0][0] = ffma2(mm0, r0, pv2[0][0]);
        pv2[0][1] = ffma2(mm0, r1, pv2[0][1]);
        pv2[0][2] = ffma2(mm0, r2, pv2[0][2]);
        pv2[0][3] = ffma2(mm0, r3, pv2[0][3]);
        pv2[1][0] = ffma2(mm1, r0, pv2[1][0]);
        pv2[1][1] = ffma2(mm1, r1, pv2[1][1]);
        pv2[1][2] = ffma2(mm1, r2, pv2[1][2]);
        pv2[1][3] = ffma2(mm1, r3, pv2[1][3]);
        pv2[2][0] = ffma2(mm2, r0, pv2[2][0]);
        pv2[2][1] = ffma2(mm2, r1, pv2[2][1]);
        pv2[2][2] = ffma2(mm2, r2, pv2[2][2]);
        pv2[2][3] = ffma2(mm2, r3, pv2[2][3]);
    }

    float sa[8], sg[8], pvv[3][8];
#pragma unroll
    for (int q = 0; q < 4; q++) {
        unpack2(psa[q], sa[2*q], sa[2*q+1]);
        unpack2(psg[q], sg[2*q], sg[2*q+1]);
    }
#pragma unroll
    for (int c = 0; c < 3; c++)
#pragma unroll
        for (int q = 0; q < 4; q++)
            unpack2(pv2[c][q], pvv[c][2*q], pvv[c][2*q+1]);

    {
        float o8[8];
#pragma unroll
        for (int i = 0; i < 8; i++) {
            float x = sa[i];
            o8[i] = __fdividef(x, 1.f + __expf(-x)) + nsv[8*h + i];
        }
        float4* p = (float4*)(out + (size_t)n * 64 + 8*h);
        p[0] = make_float4(o8[0], o8[1], o8[2], o8[3]);
        p[1] = make_float4(o8[4], o8[5], o8[6], o8[7]);
    }
    {
        float o24[24];
#pragma unroll
        for (int i = 0; i < 8; i++) {
            float g = __fdividef(1.f, 1.f + __expf(-sg[i]));
            int w = 8*h + i;
            o24[3*i+0] = pvv[0][i] * g + vin[3*w+0];
            o24[3*i+1] = pvv[1][i] * g + vin[3*w+1];
            o24[3*i+2] = pvv[2][i] * g + vin[3*w+2];
        }
        float4* p = (float4*)(out + (size_t)n * 64 + 16 + 24*h);
#pragma unroll
        for (int k = 0; k < 6; k++)
            p[k] = make_float4(o24[4*k], o24[4*k+1], o24[4*k+2], o24[4*k+3]);
    }
}

// ======================= launcher ========================================
extern "C" void kernel_launch(void* const* d_in, const int* in_sizes, int n_in,
                              void* d_out, int out_size)
{
    const float* node_scalars = (const float*)d_in[0];
    const float* node_vectors = (const float*)d_in[1];
    const float* edge_sh      = (const float*)d_in[2];
    const float* radial_emb   = (const float*)d_in[3];
    const int*   senders      = (const int*)  d_in[4];
    const int*   receivers    = (const int*)  d_in[5];
    const int*   species      = (const int*)  d_in[6];
    const float* W_in_s       = (const float*)d_in[7];
    const float* W_in_v       = (const float*)d_in[8];
    const float* mlp_w1       = (const float*)d_in[9];
    const float* mlp_b1       = (const float*)d_in[10];
    const float* mlp_w2       = (const float*)d_in[11];
    const float* W_out_s      = (const float*)d_in[12];
    const float* W_out_v      = (const float*)d_in[13];
    const float* sc_s         = (const float*)d_in[14];
    const float* sc_v         = (const float*)d_in[15];
    float* out = (float*)d_out;

    zero_kernel<<<(NN * 36 + 255) / 256, 256>>>();
    pre_kernel<<<(2 * NN + 255) / 256, 256>>>(node_scalars, node_vectors, W_in_s, W_in_v);
    edge_fused_kernel<<<1480, 256>>>(radial_emb, mlp_w1, mlp_b1, mlp_w2,
                                     edge_sh, senders, receivers);
    post_kernel<<<(2 * NN + 255) / 256, 256>>>(node_scalars, node_vectors, species,
                                               W_out_s, W_out_v, sc_s, sc_v, out);
}